// round 1
// baseline (speedup 1.0000x reference)
#include <cuda_runtime.h>

// ---------------- problem constants ----------------
#define C_DIM   2048
#define S_HEAD  64
#define NHEAD   32
#define B_SZ    8
#define T_SEQ   2048
#define M_TOK   (B_SZ * T_SEQ)            // 16384 tokens
#define BTC_N   (M_TOK * C_DIM)           // 33554432
#define BHSS_N  (B_SZ * NHEAD * S_HEAD * S_HEAD)  // 1048576

// ---------------- scratch (static device globals; no allocation allowed) ----
__device__ float g_xn [BTC_N];
__device__ float g_tmp[BTC_N];
__device__ float g_w  [BTC_N];
__device__ float g_k  [BTC_N];
__device__ float g_v  [BTC_N];
__device__ float g_r  [BTC_N];
__device__ float g_y  [BTC_N];

// ---------------- packed f32x2 helpers (B300: FFMA rt=2, f32x2 doubles rate) ----
__device__ __forceinline__ unsigned long long pk2(float lo, float hi) {
    unsigned long long r;
    asm("mov.b64 %0, {%1, %2};" : "=l"(r) : "f"(lo), "f"(hi));
    return r;
}
__device__ __forceinline__ unsigned long long fma2(unsigned long long a,
                                                   unsigned long long b,
                                                   unsigned long long c) {
    unsigned long long d;
    asm("fma.rn.f32x2 %0, %1, %2, %3;" : "=l"(d) : "l"(a), "l"(b), "l"(c));
    return d;
}
__device__ __forceinline__ float2 up2(unsigned long long v) {
    float2 f;
    asm("mov.b64 {%0, %1}, %2;" : "=f"(f.x), "=f"(f.y) : "l"(v));
    return f;
}

// ---------------- LayerNorm: one block per token row ----------------
__global__ __launch_bounds__(256) void ln_kernel(const float* __restrict__ x,
                                                 const float* __restrict__ gamma,
                                                 const float* __restrict__ beta,
                                                 float* __restrict__ xn) {
    const size_t row  = blockIdx.x;
    const float* xr   = x  + row * C_DIM;
    float*       orow = xn + row * C_DIM;
    const int base = threadIdx.x * 8;   // 256 threads * 8 = 2048

    float4 a = *(const float4*)(xr + base);
    float4 b = *(const float4*)(xr + base + 4);
    float s  = (a.x + a.y) + (a.z + a.w) + (b.x + b.y) + (b.z + b.w);
    float ss = a.x*a.x + a.y*a.y + a.z*a.z + a.w*a.w
             + b.x*b.x + b.y*b.y + b.z*b.z + b.w*b.w;

    #pragma unroll
    for (int off = 16; off > 0; off >>= 1) {
        s  += __shfl_xor_sync(0xffffffffu, s,  off);
        ss += __shfl_xor_sync(0xffffffffu, ss, off);
    }
    __shared__ float rs[8], rss[8];
    const int warp = threadIdx.x >> 5, lane = threadIdx.x & 31;
    if (lane == 0) { rs[warp] = s; rss[warp] = ss; }
    __syncthreads();
    if (warp == 0) {
        s  = (lane < 8) ? rs[lane]  : 0.0f;
        ss = (lane < 8) ? rss[lane] : 0.0f;
        #pragma unroll
        for (int off = 4; off > 0; off >>= 1) {
            s  += __shfl_xor_sync(0xffffffffu, s,  off);
            ss += __shfl_xor_sync(0xffffffffu, ss, off);
        }
        if (lane == 0) { rs[0] = s; rss[0] = ss; }
    }
    __syncthreads();
    const float mean = rs[0]  * (1.0f / C_DIM);
    const float var  = rss[0] * (1.0f / C_DIM) - mean * mean;
    const float sc   = rsqrtf(var + 1e-5f);

    float4 g0 = *(const float4*)(gamma + base);
    float4 g1 = *(const float4*)(gamma + base + 4);
    float4 e0 = *(const float4*)(beta + base);
    float4 e1 = *(const float4*)(beta + base + 4);
    float4 o0, o1;
    o0.x = (a.x - mean) * sc * g0.x + e0.x;
    o0.y = (a.y - mean) * sc * g0.y + e0.y;
    o0.z = (a.z - mean) * sc * g0.z + e0.z;
    o0.w = (a.w - mean) * sc * g0.w + e0.w;
    o1.x = (b.x - mean) * sc * g1.x + e1.x;
    o1.y = (b.y - mean) * sc * g1.y + e1.y;
    o1.z = (b.z - mean) * sc * g1.z + e1.z;
    o1.w = (b.w - mean) * sc * g1.w + e1.w;
    *(float4*)(orow + base)     = o0;
    *(float4*)(orow + base + 4) = o1;
}

// ---------------- fp32 SGEMM with packed f32x2 FMAs ----------------
// C[M,N] = epi(A[M,K] @ B[K,N] (+ bias)), row-major everywhere.
// EPI: 0 = none, 1 = sigmoid, 2 = +bias then sigmoid
#define BM 128
#define BN 128
#define BK 8

template<int EPI>
__global__ __launch_bounds__(256) void gemm_kernel(const float* __restrict__ A,
                                                   const float* __restrict__ B,
                                                   const float* __restrict__ bias,
                                                   float* __restrict__ Cmat,
                                                   int M, int N, int K) {
    __shared__ float As[BK][BM];
    __shared__ float Bs[BK][BN];

    const int tid = threadIdx.x;
    const int rm  = blockIdx.y * BM;
    const int cn  = blockIdx.x * BN;
    const int tm  = (tid >> 4) * 8;      // thread row base inside tile
    const int tn  = (tid & 15) * 8;      // thread col base inside tile

    // global load mapping
    const int arow = tid >> 1;           // 0..127
    const int akq  = (tid & 1) * 4;      // 0 or 4
    const int brow = tid >> 5;           // 0..7
    const int bc   = (tid & 31) * 4;     // 0..124

    unsigned long long acc[8][4];
    #pragma unroll
    for (int i = 0; i < 8; i++)
        #pragma unroll
        for (int j = 0; j < 4; j++) acc[i][j] = 0ull;

    const float* Aptr = A + (size_t)(rm + arow) * K + akq;
    const float* Bptr = B + (size_t)brow * N + cn + bc;

    for (int k0 = 0; k0 < K; k0 += BK) {
        float4 a4 = *(const float4*)(Aptr + k0);
        float4 b4 = *(const float4*)(Bptr + (size_t)k0 * N);
        As[akq + 0][arow] = a4.x;
        As[akq + 1][arow] = a4.y;
        As[akq + 2][arow] = a4.z;
        As[akq + 3][arow] = a4.w;
        *(float4*)&Bs[brow][bc] = b4;
        __syncthreads();

        #pragma unroll
        for (int kk = 0; kk < BK; kk++) {
            float4 a0 = *(const float4*)&As[kk][tm];
            float4 a1 = *(const float4*)&As[kk][tm + 4];
            float4 b0 = *(const float4*)&Bs[kk][tn];
            float4 b1 = *(const float4*)&Bs[kk][tn + 4];
            unsigned long long bb[4] = { pk2(b0.x, b0.y), pk2(b0.z, b0.w),
                                         pk2(b1.x, b1.y), pk2(b1.z, b1.w) };
            float av[8] = { a0.x, a0.y, a0.z, a0.w, a1.x, a1.y, a1.z, a1.w };
            #pragma unroll
            for (int i = 0; i < 8; i++) {
                unsigned long long aa = pk2(av[i], av[i]);
                #pragma unroll
                for (int j = 0; j < 4; j++)
                    acc[i][j] = fma2(aa, bb[j], acc[i][j]);
            }
        }
        __syncthreads();
    }

    #pragma unroll
    for (int i = 0; i < 8; i++) {
        float outv[8];
        #pragma unroll
        for (int j = 0; j < 4; j++) {
            float2 f = up2(acc[i][j]);
            outv[2 * j]     = f.x;
            outv[2 * j + 1] = f.y;
        }
        const int grow = rm + tm + i;
        const int gcol = cn + tn;
        #pragma unroll
        for (int j = 0; j < 8; j++) {
            float val = outv[j];
            if (EPI >= 2) val += bias[gcol + j];
            if (EPI >= 1) val = 1.0f / (1.0f + __expf(-val));
            outv[j] = val;
        }
        *(float4*)&Cmat[(size_t)grow * N + gcol] =
            make_float4(outv[0], outv[1], outv[2], outv[3]);
        *(float4*)&Cmat[(size_t)grow * N + gcol + 4] =
            make_float4(outv[4], outv[5], outv[6], outv[7]);
    }
}

// ---------------- selective WKV scan ----------------
// One block per (b,h); 64 threads, thread t owns state column t (64 rows in regs).
// state[s,t] = (1-w[s])*state[s,t] + k[s]*v[t];  y[t] = sum_s r[s]*state[s,t]
__global__ __launch_bounds__(64) void wkv_scan(const float* __restrict__ w,
                                               const float* __restrict__ k,
                                               const float* __restrict__ v,
                                               const float* __restrict__ r,
                                               float* __restrict__ y,
                                               float* __restrict__ state_out,
                                               int write_state) {
    const int bh = blockIdx.x;
    const int b  = bh / NHEAD;
    const int h  = bh % NHEAD;
    const int t  = threadIdx.x;   // column index 0..63

    __shared__ float shw[2][S_HEAD];
    __shared__ float shk[2][S_HEAD];
    __shared__ float shr[2][S_HEAD];

    float st[S_HEAD];
    #pragma unroll
    for (int s = 0; s < S_HEAD; s++) st[s] = 0.0f;

    const size_t base = (size_t)b * T_SEQ * C_DIM + (size_t)h * S_HEAD + t;

    // prefetch step 0
    float pw = w[base], pk = k[base], pv = v[base], pr = r[base];
    int buf = 0;

    for (int step = 0; step < T_SEQ; ++step) {
        shw[buf][t] = 1.0f - pw;
        shk[buf][t] = pk;
        shr[buf][t] = pr;
        const float vt = pv;
        __syncthreads();

        // software prefetch next step (hides DRAM latency behind FMA work)
        if (step + 1 < T_SEQ) {
            const size_t nb = base + (size_t)(step + 1) * C_DIM;
            pw = w[nb]; pk = k[nb]; pv = v[nb]; pr = r[nb];
        }

        float y0 = 0.f, y1 = 0.f, y2 = 0.f, y3 = 0.f;
        #pragma unroll
        for (int s = 0; s < S_HEAD; s += 4) {
            st[s]     = st[s]     * shw[buf][s]     + shk[buf][s]     * vt;
            y0 += shr[buf][s]     * st[s];
            st[s + 1] = st[s + 1] * shw[buf][s + 1] + shk[buf][s + 1] * vt;
            y1 += shr[buf][s + 1] * st[s + 1];
            st[s + 2] = st[s + 2] * shw[buf][s + 2] + shk[buf][s + 2] * vt;
            y2 += shr[buf][s + 2] * st[s + 2];
            st[s + 3] = st[s + 3] * shw[buf][s + 3] + shk[buf][s + 3] * vt;
            y3 += shr[buf][s + 3] * st[s + 3];
        }
        y[base + (size_t)step * C_DIM] = (y0 + y1) + (y2 + y3);
        buf ^= 1;
    }

    if (write_state) {
        // state_f layout [B,H,S,S]: ((b*H + h)*S + s)*S + t
        #pragma unroll
        for (int s = 0; s < S_HEAD; s++)
            state_out[((size_t)bh * S_HEAD + s) * S_HEAD + t] = st[s];
    }
}

// ---------------- launch ----------------
extern "C" void kernel_launch(void* const* d_in, const int* in_sizes, int n_in,
                              void* d_out, int out_size) {
    const float* x     = (const float*)d_in[0];
    const float* Wx    = (const float*)d_in[1];
    const float* Ww    = (const float*)d_in[2];
    const float* bw    = (const float*)d_in[3];
    const float* Wk    = (const float*)d_in[4];
    const float* Wv    = (const float*)d_in[5];
    const float* Wr    = (const float*)d_in[6];
    const float* Wo    = (const float*)d_in[7];
    const float* gamma = (const float*)d_in[8];
    const float* beta  = (const float*)d_in[9];
    float* out = (float*)d_out;

    float *xn, *tmp, *w, *k, *v, *r, *y;
    cudaGetSymbolAddress((void**)&xn,  g_xn);
    cudaGetSymbolAddress((void**)&tmp, g_tmp);
    cudaGetSymbolAddress((void**)&w,   g_w);
    cudaGetSymbolAddress((void**)&k,   g_k);
    cudaGetSymbolAddress((void**)&v,   g_v);
    cudaGetSymbolAddress((void**)&r,   g_r);
    cudaGetSymbolAddress((void**)&y,   g_y);

    ln_kernel<<<M_TOK, 256>>>(x, gamma, beta, xn);

    dim3 grid(C_DIM / BN, M_TOK / BM);   // (16, 128)
    gemm_kernel<0><<<grid, 256>>>(xn,  Wx, nullptr, tmp, M_TOK, C_DIM, C_DIM);
    gemm_kernel<2><<<grid, 256>>>(tmp, Ww, bw,      w,   M_TOK, C_DIM, C_DIM);
    gemm_kernel<0><<<grid, 256>>>(xn,  Wk, nullptr, k,   M_TOK, C_DIM, C_DIM);
    gemm_kernel<0><<<grid, 256>>>(xn,  Wv, nullptr, v,   M_TOK, C_DIM, C_DIM);
    gemm_kernel<1><<<grid, 256>>>(xn,  Wr, nullptr, r,   M_TOK, C_DIM, C_DIM);

    const int write_state = (out_size >= (BTC_N + BHSS_N)) ? 1 : 0;
    wkv_scan<<<B_SZ * NHEAD, S_HEAD>>>(w, k, v, r, y, out + BTC_N, write_state);

    gemm_kernel<0><<<grid, 256>>>(y, Wo, nullptr, out, M_TOK, C_DIM, C_DIM);
}

// round 2
// speedup vs baseline: 1.0022x; 1.0022x over previous
#include <cuda_runtime.h>

// ---------------- problem constants ----------------
#define C_DIM   2048
#define S_HEAD  64
#define NHEAD   32
#define B_SZ    8
#define T_SEQ   2048
#define M_TOK   (B_SZ * T_SEQ)            // 16384 tokens
#define BTC_N   (M_TOK * C_DIM)           // 33554432
#define BHSS_N  (B_SZ * NHEAD * S_HEAD * S_HEAD)  // 1048576

// ---------------- scratch (static device globals; no allocation allowed) ----
__device__ float g_xn [BTC_N];
__device__ float g_tmp[BTC_N];
__device__ float g_w  [BTC_N];
__device__ float g_k  [BTC_N];
__device__ float g_v  [BTC_N];
__device__ float g_r  [BTC_N];
__device__ float g_y  [BTC_N];

// ---------------- packed f32x2 helpers (B300: FFMA rt=2, f32x2 doubles rate) ----
__device__ __forceinline__ unsigned long long pk2(float lo, float hi) {
    unsigned long long r;
    asm("mov.b64 %0, {%1, %2};" : "=l"(r) : "f"(lo), "f"(hi));
    return r;
}
__device__ __forceinline__ unsigned long long fma2(unsigned long long a,
                                                   unsigned long long b,
                                                   unsigned long long c) {
    unsigned long long d;
    asm("fma.rn.f32x2 %0, %1, %2, %3;" : "=l"(d) : "l"(a), "l"(b), "l"(c));
    return d;
}
__device__ __forceinline__ float2 up2(unsigned long long v) {
    float2 f;
    asm("mov.b64 {%0, %1}, %2;" : "=f"(f.x), "=f"(f.y) : "l"(v));
    return f;
}

// ---------------- LayerNorm: one block per token row ----------------
__global__ __launch_bounds__(256) void ln_kernel(const float* __restrict__ x,
                                                 const float* __restrict__ gamma,
                                                 const float* __restrict__ beta,
                                                 float* __restrict__ xn) {
    const size_t row  = blockIdx.x;
    const float* xr   = x  + row * C_DIM;
    float*       orow = xn + row * C_DIM;
    const int base = threadIdx.x * 8;   // 256 threads * 8 = 2048

    float4 a = *(const float4*)(xr + base);
    float4 b = *(const float4*)(xr + base + 4);
    float s  = (a.x + a.y) + (a.z + a.w) + (b.x + b.y) + (b.z + b.w);
    float ss = a.x*a.x + a.y*a.y + a.z*a.z + a.w*a.w
             + b.x*b.x + b.y*b.y + b.z*b.z + b.w*b.w;

    #pragma unroll
    for (int off = 16; off > 0; off >>= 1) {
        s  += __shfl_xor_sync(0xffffffffu, s,  off);
        ss += __shfl_xor_sync(0xffffffffu, ss, off);
    }
    __shared__ float rs[8], rss[8];
    const int warp = threadIdx.x >> 5, lane = threadIdx.x & 31;
    if (lane == 0) { rs[warp] = s; rss[warp] = ss; }
    __syncthreads();
    if (warp == 0) {
        s  = (lane < 8) ? rs[lane]  : 0.0f;
        ss = (lane < 8) ? rss[lane] : 0.0f;
        #pragma unroll
        for (int off = 4; off > 0; off >>= 1) {
            s  += __shfl_xor_sync(0xffffffffu, s,  off);
            ss += __shfl_xor_sync(0xffffffffu, ss, off);
        }
        if (lane == 0) { rs[0] = s; rss[0] = ss; }
    }
    __syncthreads();
    const float mean = rs[0]  * (1.0f / C_DIM);
    const float var  = rss[0] * (1.0f / C_DIM) - mean * mean;
    const float sc   = rsqrtf(var + 1e-5f);

    float4 g0 = *(const float4*)(gamma + base);
    float4 g1 = *(const float4*)(gamma + base + 4);
    float4 e0 = *(const float4*)(beta + base);
    float4 e1 = *(const float4*)(beta + base + 4);
    float4 o0, o1;
    o0.x = (a.x - mean) * sc * g0.x + e0.x;
    o0.y = (a.y - mean) * sc * g0.y + e0.y;
    o0.z = (a.z - mean) * sc * g0.z + e0.z;
    o0.w = (a.w - mean) * sc * g0.w + e0.w;
    o1.x = (b.x - mean) * sc * g1.x + e1.x;
    o1.y = (b.y - mean) * sc * g1.y + e1.y;
    o1.z = (b.z - mean) * sc * g1.z + e1.z;
    o1.w = (b.w - mean) * sc * g1.w + e1.w;
    *(float4*)(orow + base)     = o0;
    *(float4*)(orow + base + 4) = o1;
}

// ---------------- fp32 SGEMM with packed f32x2 FMAs ----------------
// C[M,N] = epi(A[M,K] @ B[K,N] (+ bias)), row-major everywhere.
// EPI: 0 = none, 1 = sigmoid, 2 = +bias then sigmoid
#define BM 128
#define BN 128
#define BK 8

template<int EPI>
__global__ __launch_bounds__(256) void gemm_kernel(const float* __restrict__ A,
                                                   const float* __restrict__ B,
                                                   const float* __restrict__ bias,
                                                   float* __restrict__ Cmat,
                                                   int M, int N, int K) {
    __shared__ float As[BK][BM];
    __shared__ float Bs[BK][BN];

    const int tid = threadIdx.x;
    const int rm  = blockIdx.y * BM;
    const int cn  = blockIdx.x * BN;
    const int tm  = (tid >> 4) * 8;      // thread row base inside tile
    const int tn  = (tid & 15) * 8;      // thread col base inside tile

    // global load mapping
    const int arow = tid >> 1;           // 0..127
    const int akq  = (tid & 1) * 4;      // 0 or 4
    const int brow = tid >> 5;           // 0..7
    const int bc   = (tid & 31) * 4;     // 0..124

    unsigned long long acc[8][4];
    #pragma unroll
    for (int i = 0; i < 8; i++)
        #pragma unroll
        for (int j = 0; j < 4; j++) acc[i][j] = 0ull;

    const float* Aptr = A + (size_t)(rm + arow) * K + akq;
    const float* Bptr = B + (size_t)brow * N + cn + bc;

    for (int k0 = 0; k0 < K; k0 += BK) {
        float4 a4 = *(const float4*)(Aptr + k0);
        float4 b4 = *(const float4*)(Bptr + (size_t)k0 * N);
        As[akq + 0][arow] = a4.x;
        As[akq + 1][arow] = a4.y;
        As[akq + 2][arow] = a4.z;
        As[akq + 3][arow] = a4.w;
        *(float4*)&Bs[brow][bc] = b4;
        __syncthreads();

        #pragma unroll
        for (int kk = 0; kk < BK; kk++) {
            float4 a0 = *(const float4*)&As[kk][tm];
            float4 a1 = *(const float4*)&As[kk][tm + 4];
            float4 b0 = *(const float4*)&Bs[kk][tn];
            float4 b1 = *(const float4*)&Bs[kk][tn + 4];
            unsigned long long bb[4] = { pk2(b0.x, b0.y), pk2(b0.z, b0.w),
                                         pk2(b1.x, b1.y), pk2(b1.z, b1.w) };
            float av[8] = { a0.x, a0.y, a0.z, a0.w, a1.x, a1.y, a1.z, a1.w };
            #pragma unroll
            for (int i = 0; i < 8; i++) {
                unsigned long long aa = pk2(av[i], av[i]);
                #pragma unroll
                for (int j = 0; j < 4; j++)
                    acc[i][j] = fma2(aa, bb[j], acc[i][j]);
            }
        }
        __syncthreads();
    }

    #pragma unroll
    for (int i = 0; i < 8; i++) {
        float outv[8];
        #pragma unroll
        for (int j = 0; j < 4; j++) {
            float2 f = up2(acc[i][j]);
            outv[2 * j]     = f.x;
            outv[2 * j + 1] = f.y;
        }
        const int grow = rm + tm + i;
        const int gcol = cn + tn;
        #pragma unroll
        for (int j = 0; j < 8; j++) {
            float val = outv[j];
            if (EPI >= 2) val += bias[gcol + j];
            if (EPI >= 1) val = 1.0f / (1.0f + __expf(-val));
            outv[j] = val;
        }
        *(float4*)&Cmat[(size_t)grow * N + gcol] =
            make_float4(outv[0], outv[1], outv[2], outv[3]);
        *(float4*)&Cmat[(size_t)grow * N + gcol + 4] =
            make_float4(outv[4], outv[5], outv[6], outv[7]);
    }
}

// ---------------- selective WKV scan ----------------
// One block per (b,h); 64 threads, thread t owns state column t (64 rows in regs).
// state[s,t] = (1-w[s])*state[s,t] + k[s]*v[t];  y[t] = sum_s r[s]*state[s,t]
__global__ __launch_bounds__(64) void wkv_scan(const float* __restrict__ w,
                                               const float* __restrict__ k,
                                               const float* __restrict__ v,
                                               const float* __restrict__ r,
                                               float* __restrict__ y,
                                               float* __restrict__ state_out,
                                               int write_state) {
    const int bh = blockIdx.x;
    const int b  = bh / NHEAD;
    const int h  = bh % NHEAD;
    const int t  = threadIdx.x;   // column index 0..63

    __shared__ float shw[2][S_HEAD];
    __shared__ float shk[2][S_HEAD];
    __shared__ float shr[2][S_HEAD];

    float st[S_HEAD];
    #pragma unroll
    for (int s = 0; s < S_HEAD; s++) st[s] = 0.0f;

    const size_t base = (size_t)b * T_SEQ * C_DIM + (size_t)h * S_HEAD + t;

    // prefetch step 0
    float pw = w[base], pk = k[base], pv = v[base], pr = r[base];
    int buf = 0;

    for (int step = 0; step < T_SEQ; ++step) {
        shw[buf][t] = 1.0f - pw;
        shk[buf][t] = pk;
        shr[buf][t] = pr;
        const float vt = pv;
        __syncthreads();

        // software prefetch next step (hides DRAM latency behind FMA work)
        if (step + 1 < T_SEQ) {
            const size_t nb = base + (size_t)(step + 1) * C_DIM;
            pw = w[nb]; pk = k[nb]; pv = v[nb]; pr = r[nb];
        }

        float y0 = 0.f, y1 = 0.f, y2 = 0.f, y3 = 0.f;
        #pragma unroll
        for (int s = 0; s < S_HEAD; s += 4) {
            st[s]     = st[s]     * shw[buf][s]     + shk[buf][s]     * vt;
            y0 += shr[buf][s]     * st[s];
            st[s + 1] = st[s + 1] * shw[buf][s + 1] + shk[buf][s + 1] * vt;
            y1 += shr[buf][s + 1] * st[s + 1];
            st[s + 2] = st[s + 2] * shw[buf][s + 2] + shk[buf][s + 2] * vt;
            y2 += shr[buf][s + 2] * st[s + 2];
            st[s + 3] = st[s + 3] * shw[buf][s + 3] + shk[buf][s + 3] * vt;
            y3 += shr[buf][s + 3] * st[s + 3];
        }
        y[base + (size_t)step * C_DIM] = (y0 + y1) + (y2 + y3);
        buf ^= 1;
    }

    if (write_state) {
        // state_f layout [B,H,S,S]: ((b*H + h)*S + s)*S + t
        #pragma unroll
        for (int s = 0; s < S_HEAD; s++)
            state_out[((size_t)bh * S_HEAD + s) * S_HEAD + t] = st[s];
    }
}

// ---------------- launch ----------------
extern "C" void kernel_launch(void* const* d_in, const int* in_sizes, int n_in,
                              void* d_out, int out_size) {
    const float* x     = (const float*)d_in[0];
    const float* Wx    = (const float*)d_in[1];
    const float* Ww    = (const float*)d_in[2];
    const float* bw    = (const float*)d_in[3];
    const float* Wk    = (const float*)d_in[4];
    const float* Wv    = (const float*)d_in[5];
    const float* Wr    = (const float*)d_in[6];
    const float* Wo    = (const float*)d_in[7];
    const float* gamma = (const float*)d_in[8];
    const float* beta  = (const float*)d_in[9];
    float* out = (float*)d_out;

    float *xn, *tmp, *w, *k, *v, *r, *y;
    cudaGetSymbolAddress((void**)&xn,  g_xn);
    cudaGetSymbolAddress((void**)&tmp, g_tmp);
    cudaGetSymbolAddress((void**)&w,   g_w);
    cudaGetSymbolAddress((void**)&k,   g_k);
    cudaGetSymbolAddress((void**)&v,   g_v);
    cudaGetSymbolAddress((void**)&r,   g_r);
    cudaGetSymbolAddress((void**)&y,   g_y);

    ln_kernel<<<M_TOK, 256>>>(x, gamma, beta, xn);

    dim3 grid(C_DIM / BN, M_TOK / BM);   // (16, 128)
    gemm_kernel<0><<<grid, 256>>>(xn,  Wx, nullptr, tmp, M_TOK, C_DIM, C_DIM);
    gemm_kernel<2><<<grid, 256>>>(tmp, Ww, bw,      w,   M_TOK, C_DIM, C_DIM);
    gemm_kernel<0><<<grid, 256>>>(xn,  Wk, nullptr, k,   M_TOK, C_DIM, C_DIM);
    gemm_kernel<0><<<grid, 256>>>(xn,  Wv, nullptr, v,   M_TOK, C_DIM, C_DIM);
    gemm_kernel<1><<<grid, 256>>>(xn,  Wr, nullptr, r,   M_TOK, C_DIM, C_DIM);

    const int write_state = (out_size >= (BTC_N + BHSS_N)) ? 1 : 0;
    wkv_scan<<<B_SZ * NHEAD, S_HEAD>>>(w, k, v, r, y, out + BTC_N, write_state);

    gemm_kernel<0><<<grid, 256>>>(y, Wo, nullptr, out, M_TOK, C_DIM, C_DIM);
}